// round 15
// baseline (speedup 1.0000x reference)
#include <cuda_runtime.h>
#include <cuda_fp16.h>
#include <cstdint>

#define NN 21
#define D 256
#define GH 512
#define NE 40
#define NB 8192
#define M_TOTAL (NB * NN)     /* 172032 */
#define NCAT 1280
#define LN_EPS 1e-5f

#define MTB 3                 /* batches per CTA */
#define ROWS 63               /* valid rows per CTA */
#define MT 64                 /* M tile (1 pad row) */
#define NBLK ((NB + MTB - 1) / MTB)   /* 2731 */

#define NTC 128               /* N chunk */
#define KC 64                 /* K per B stage */
#define NITER 40              /* 10 chunks x 4 k-steps */

#define A_STRH 264
#define B_STRH 72
#define ST_STRH 136
#define V_STRH 264

/* smem layout (bytes) */
#define OFF_A   0
#define SZ_A    (MT * A_STRH * 2)            /* 33792 */
#define OFF_B   (OFF_A + SZ_A)
#define SZ_B    (2 * NTC * B_STRH * 2)       /* 36864; V (63*264*2=33264) overlays after loop */
#define OFF_ST  (OFF_B + SZ_B)
#define SZ_ST   (MT * ST_STRH * 2)           /* 17408 */
#define OFF_W2  (OFF_ST + SZ_ST)
#define OFF_GATE (OFF_W2 + GH * 4)
#define OFF_IDX (OFF_GATE + 128 * 4)
#define FUSED_SMEM (OFF_IDX + 1024)          /* ~92 KB -> 2 CTAs/SM */

// ---------------- scratch ----------------
__device__ __half g_WcatT[(size_t)NCAT * D];  /* reordered [n][k]: A0 B0 ... | V */
__device__ float  g_bias[NCAT];
__device__ int    g_bStart[NN + 1];
__device__ int    g_bEdge[NE];

// ---------------- helpers ----------------
__device__ __forceinline__ void cp_async16(void* smem, const void* gmem) {
    unsigned s = (unsigned)__cvta_generic_to_shared(smem);
    asm volatile("cp.async.cg.shared.global [%0], [%1], 16;\n" :: "r"(s), "l"(gmem));
}
__device__ __forceinline__ float gelu_t(float x) {
    float u = 0.7978845608f * fmaf(0.044715f * x, x * x, x);
    float e = __expf(2.f * u);
    float th = 1.f - __fdividef(2.f, e + 1.f);
    return 0.5f * x * (1.f + th);
}
__device__ __forceinline__ void mma16(float* d, const unsigned* a, const unsigned* b) {
    asm volatile(
        "mma.sync.aligned.m16n8k16.row.col.f32.f16.f16.f32 "
        "{%0,%1,%2,%3}, {%4,%5,%6,%7}, {%8,%9}, {%0,%1,%2,%3};\n"
        : "+f"(d[0]), "+f"(d[1]), "+f"(d[2]), "+f"(d[3])
        : "r"(a[0]), "r"(a[1]), "r"(a[2]), "r"(a[3]), "r"(b[0]), "r"(b[1]));
}
__device__ __forceinline__ void ldsm4(unsigned* r, uint32_t addr) {
    asm volatile("ldmatrix.sync.aligned.m8n8.x4.shared.b16 {%0,%1,%2,%3}, [%4];"
        : "=r"(r[0]), "=r"(r[1]), "=r"(r[2]), "=r"(r[3]) : "r"(addr));
}

// ---------------- kernel 0: interleaved weights + bias + edge buckets ----------------
__global__ void prep_kernel(const float* __restrict__ Wv, const float* __restrict__ bv,
                            const float* __restrict__ W1, const float* __restrict__ b1,
                            const int* __restrict__ srcI, const int* __restrict__ dstI) {
    int idx = blockIdx.x * blockDim.x + threadIdx.x;
    if (idx < D * NCAT) {
        int k = idx / NCAT, n = idx % NCAT;
        float w;
        if (n < 1024) {
            int j = n >> 1;
            w = (n & 1) ? W1[(256 + k) * 512 + j] : W1[k * 512 + j];
        } else {
            w = Wv[k * 256 + (n - 1024)];
        }
        g_WcatT[(size_t)n * D + k] = __float2half_rn(w);
    }
    if (idx < NCAT) {
        float bb;
        if (idx < 1024) bb = (idx & 1) ? 0.f : b1[idx >> 1];
        else            bb = bv[idx - 1024];
        g_bias[idx] = bb;
    }
    if (blockIdx.x == 0 && threadIdx.x == 0) {
        int cnt[NN];
        for (int n = 0; n < NN; n++) cnt[n] = 0;
        for (int e = 0; e < NE; e++) cnt[dstI[e]]++;
        g_bStart[0] = 0;
        for (int n = 0; n < NN; n++) g_bStart[n + 1] = g_bStart[n] + cnt[n];
        int pos[NN];
        for (int n = 0; n < NN; n++) pos[n] = g_bStart[n];
        for (int e = 0; e < NE; e++) g_bEdge[pos[dstI[e]]++] = e;
    }
}

// ---------------- fused kernel: LN + GEMM + gates + scatter ----------------
__device__ __forceinline__ void load_B_stage(__half* sB, int tid, int idx) {
    int nb = (idx >> 2) * NTC, kb = (idx & 3) * KC;
    __half* Bst = sB + (idx & 1) * (NTC * B_STRH);
    #pragma unroll
    for (int t = 0; t < 4; t++) {                 /* 1024 x 16B chunks / 256 thr */
        int ch = tid + (t << 8);
        int row = ch >> 3, c8 = (ch & 7) * 8;
        cp_async16((char*)Bst + row * (B_STRH * 2) + c8 * 2,
                   g_WcatT + (size_t)(nb + row) * D + kb + c8);
    }
    asm volatile("cp.async.commit_group;\n");
}

__global__ __launch_bounds__(256, 2) void fused_kernel(
    const float* __restrict__ h, const int* __restrict__ srcI, const int* __restrict__ dstI,
    const float* __restrict__ lnw, const float* __restrict__ lnb,
    const float* __restrict__ W2, const float* __restrict__ b2, float* __restrict__ out) {
    extern __shared__ __align__(16) char smem[];
    __half* sA  = (__half*)(smem + OFF_A);
    __half* sB  = (__half*)(smem + OFF_B);
    __half* sV  = (__half*)(smem + OFF_B);        /* overlays sB after main loop */
    __half* sSt = (__half*)(smem + OFF_ST);
    float*  sW2 = (float*)(smem + OFF_W2);
    float*  sGA = (float*)(smem + OFF_GATE);
    int* sSrc = (int*)(smem + OFF_IDX);
    int* sDst = sSrc + NE;
    int* sBS  = sDst + NE;
    int* sBE  = sBS + NN + 1;

    const int tid = threadIdx.x, warp = tid >> 5, lane = tid & 31;
    const int wm = warp & 1, wn = warp >> 1;      /* warp tile 32 rows x 32 cols */
    const int gq = lane >> 2, t = lane & 3;
    const int rowBase = blockIdx.x * ROWS;
    const int validB = min(MTB, NB - blockIdx.x * MTB);
    const int vrows = validB * NN;
    const uint32_t sAu = (uint32_t)__cvta_generic_to_shared(sA);
    const uint32_t sBu = (uint32_t)__cvta_generic_to_shared(sB);

    if (tid < NE) { sSrc[tid] = srcI[tid]; sDst[tid] = dstI[tid]; sBE[tid] = g_bEdge[tid]; }
    if (tid >= 64 && tid < 64 + NN + 1) sBS[tid - 64] = g_bStart[tid - 64];
    if (tid < 128) ((float4*)sW2)[tid] = ((const float4*)W2)[tid];
    if (tid < MTB * NE) sGA[tid] = 0.f;

    load_B_stage(sB, tid, 0);

    /* fused LayerNorm: warp per row, 8 rows/warp, fp16 into sA */
    {
        float4 w0 = ((const float4*)lnw)[2 * lane], w1 = ((const float4*)lnw)[2 * lane + 1];
        float4 bb0 = ((const float4*)lnb)[2 * lane], bb1 = ((const float4*)lnb)[2 * lane + 1];
        #pragma unroll 2
        for (int it = 0; it < 8; it++) {
            int row = warp * 8 + it;
            int gRow = rowBase + row; if (gRow > M_TOTAL - 1) gRow = M_TOTAL - 1;
            const float4* r4 = (const float4*)(h + (size_t)gRow * D);
            float4 va = r4[2 * lane], vb = r4[2 * lane + 1];
            float s = va.x + va.y + va.z + va.w + vb.x + vb.y + vb.z + vb.w;
            float q = va.x*va.x + va.y*va.y + va.z*va.z + va.w*va.w
                    + vb.x*vb.x + vb.y*vb.y + vb.z*vb.z + vb.w*vb.w;
            #pragma unroll
            for (int off = 16; off; off >>= 1) {
                s += __shfl_xor_sync(0xffffffffu, s, off);
                q += __shfl_xor_sync(0xffffffffu, q, off);
            }
            float mu = s * (1.f / D);
            float var = q * (1.f / D) - mu * mu;
            float inv = rsqrtf(var + LN_EPS);
            __half2 h0 = __floats2half2_rn((va.x - mu) * inv * w0.x + bb0.x,
                                           (va.y - mu) * inv * w0.y + bb0.y);
            __half2 h1 = __floats2half2_rn((va.z - mu) * inv * w0.z + bb0.z,
                                           (va.w - mu) * inv * w0.w + bb0.w);
            __half2 h2 = __floats2half2_rn((vb.x - mu) * inv * w1.x + bb1.x,
                                           (vb.y - mu) * inv * w1.y + bb1.y);
            __half2 h3 = __floats2half2_rn((vb.z - mu) * inv * w1.z + bb1.z,
                                           (vb.w - mu) * inv * w1.w + bb1.w);
            uint4 o;
            o.x = *(unsigned*)&h0; o.y = *(unsigned*)&h1;
            o.z = *(unsigned*)&h2; o.w = *(unsigned*)&h3;
            *(uint4*)(sA + row * A_STRH + lane * 8) = o;
        }
    }

    const int lm = lane >> 3, lr = lane & 7;
    uint32_t aBase[2], bOff[2];
    #pragma unroll
    for (int mi = 0; mi < 2; mi++)
        aBase[mi] = sAu + (uint32_t)(((wm * 32 + mi * 16 + (lm & 1) * 8 + lr) * A_STRH
                                      + (lm >> 1) * 8) * 2);
    #pragma unroll
    for (int nj = 0; nj < 2; nj++)
        bOff[nj] = (uint32_t)(((wn * 32 + nj * 16 + (lm >> 1) * 8 + lr) * B_STRH
                               + (lm & 1) * 8) * 2);

    float c[2][4][4];
    #pragma unroll 1
    for (int chunk = 0; chunk < 10; chunk++) {
        #pragma unroll
        for (int mi = 0; mi < 2; mi++)
            #pragma unroll
            for (int ni = 0; ni < 4; ni++)
                #pragma unroll
                for (int j = 0; j < 4; j++) c[mi][ni][j] = 0.f;

        #pragma unroll
        for (int kc = 0; kc < 4; kc++) {
            int i = chunk * 4 + kc;
            asm volatile("cp.async.wait_group 0;\n" ::: "memory");
            __syncthreads();
            if (i + 1 < NITER) load_B_stage(sB, tid, i + 1);

            uint32_t stB = sBu + (uint32_t)((kc & 1) * (NTC * B_STRH) * 2);
            #pragma unroll
            for (int ks = 0; ks < 4; ks++) {
                unsigned af[2][4], bf[2][4];
                uint32_t ka = (uint32_t)((kc * KC + ks * 16) * 2);
                uint32_t kb = (uint32_t)((ks * 16) * 2);
                ldsm4(af[0], aBase[0] + ka);
                ldsm4(af[1], aBase[1] + ka);
                ldsm4(bf[0], stB + bOff[0] + kb);
                ldsm4(bf[1], stB + bOff[1] + kb);
                #pragma unroll
                for (int mi = 0; mi < 2; mi++)
                    #pragma unroll
                    for (int nj = 0; nj < 2; nj++) {
                        mma16(c[mi][2 * nj],     af[mi], &bf[nj][0]);
                        mma16(c[mi][2 * nj + 1], af[mi], &bf[nj][2]);
                    }
            }
        }

        if (chunk < 9) {
            /* epilogue -> stage (gate chunks 0-7 and V chunk 8), bias added */
            int nBase = chunk * NTC;
            #pragma unroll
            for (int mi = 0; mi < 2; mi++)
                #pragma unroll
                for (int ni = 0; ni < 4; ni++) {
                    int r0 = wm * 32 + mi * 16 + gq;
                    int cb = wn * 32 + ni * 8 + 2 * t;
                    float b0v = g_bias[nBase + cb], b1v = g_bias[nBase + cb + 1];
                    *(__half2*)&sSt[r0 * ST_STRH + cb] =
                        __floats2half2_rn(c[mi][ni][0] + b0v, c[mi][ni][1] + b1v);
                    *(__half2*)&sSt[(r0 + 8) * ST_STRH + cb] =
                        __floats2half2_rn(c[mi][ni][2] + b0v, c[mi][ni][3] + b1v);
                }
            if (chunk < 8) {
                __syncthreads();
                /* gate phase: 64 pairs of this chunk; combo = warp*15 + k */
                #pragma unroll 1
                for (int k = 0; k < 15; k++) {
                    int combo = warp * 15 + k;
                    int be = combo / NE, e = combo - be * NE;
                    int sR = be * NN + sSrc[e], dR = be * NN + sDst[e];
                    float sum = 0.f;
                    #pragma unroll
                    for (int rep = 0; rep < 2; rep++) {
                        int jl = lane + (rep << 5);
                        float a = __half2float(sSt[sR * ST_STRH + 2 * jl]);
                        float b = __half2float(sSt[dR * ST_STRH + 2 * jl + 1]);
                        sum += gelu_t(a + b) * sW2[(chunk << 6) + jl];
                    }
                    #pragma unroll
                    for (int off = 16; off; off >>= 1)
                        sum += __shfl_xor_sync(0xffffffffu, sum, off);
                    if (!lane) sGA[combo] += sum;
                }
            }
            /* chunk 8 (V cols 0-127): stays in stage until after the loop */
        } else {
            /* chunk 9 (V cols 128-255): reclaim sB area as sV */
            __syncthreads();   /* all warps done reading B stages */
            #pragma unroll
            for (int mi = 0; mi < 2; mi++)
                #pragma unroll
                for (int ni = 0; ni < 4; ni++) {
                    int r0 = wm * 32 + mi * 16 + gq;
                    int cb = wn * 32 + ni * 8 + 2 * t;
                    float b0v = g_bias[1152 + cb], b1v = g_bias[1152 + cb + 1];
                    if (r0 < ROWS)
                        *(__half2*)&sV[r0 * V_STRH + 128 + cb] =
                            __floats2half2_rn(c[mi][ni][0] + b0v, c[mi][ni][1] + b1v);
                    if (r0 + 8 < ROWS)
                        *(__half2*)&sV[(r0 + 8) * V_STRH + 128 + cb] =
                            __floats2half2_rn(c[mi][ni][2] + b0v, c[mi][ni][3] + b1v);
                }
            /* copy stage (V cols 0-127) -> sV: 63 rows x 16 uint4 (8 halves each) */
            #pragma unroll
            for (int w2i = 0; w2i < 4; w2i++) {
                int idx = tid + (w2i << 8);     /* 1024 tasks: row 0..63 x 16 groups */
                int row = idx >> 4, grp = idx & 15;
                if (row < ROWS)
                    *(uint4*)&sV[row * V_STRH + grp * 8] =
                        *(const uint4*)&sSt[row * ST_STRH + grp * 8];
            }
        }
    }

    __syncthreads();
    if (tid < MTB * NE)
        sGA[tid] = 1.f / (1.f + __expf(-(sGA[tid] + __ldg(b2))));
    __syncthreads();

    /* scatter + residual: thread = float4 column, 4 row-slots */
    const float* hb = h + (size_t)rowBase * D;
    float* ob = out + (size_t)rowBase * D;
    int col = tid & 63, slot = tid >> 6;
    #pragma unroll 1
    for (int task = slot; task < vrows; task += 4) {
        int be = task / NN, n = task - be * NN;
        float4 acc = ((const float4*)(hb + task * D))[col];
        int jEnd = sBS[n + 1];
        for (int jj = sBS[n]; jj < jEnd; jj++) {
            int e = sBE[jj];
            float gte = sGA[be * NE + e];
            const __half* vp = sV + (be * NN + sSrc[e]) * V_STRH + col * 4;
            uint2 u = *(const uint2*)vp;
            float2 lo = __half22float2(*(__half2*)&u.x);
            float2 hi = __half22float2(*(__half2*)&u.y);
            acc.x += gte * lo.x; acc.y += gte * lo.y;
            acc.z += gte * hi.x; acc.w += gte * hi.y;
        }
        ((float4*)(ob + task * D))[col] = acc;
    }
}

// ---------------- launcher ----------------
extern "C" void kernel_launch(void* const* d_in, const int* in_sizes, int n_in,
                              void* d_out, int out_size) {
    const float* h    = (const float*)d_in[0];
    const int*   srcI = (const int*)d_in[1];
    const int*   dstI = (const int*)d_in[2];
    const float* ln_w = (const float*)d_in[3];
    const float* ln_b = (const float*)d_in[4];
    const float* Wv   = (const float*)d_in[5];
    const float* bv   = (const float*)d_in[6];
    const float* W1   = (const float*)d_in[7];
    const float* b1   = (const float*)d_in[8];
    const float* W2   = (const float*)d_in[9];
    const float* b2   = (const float*)d_in[10];
    float* out = (float*)d_out;

    cudaFuncSetAttribute(fused_kernel, cudaFuncAttributeMaxDynamicSharedMemorySize, FUSED_SMEM);

    prep_kernel<<<(D * NCAT + 255) / 256, 256>>>(Wv, bv, W1, b1, srcI, dstI);
    fused_kernel<<<NBLK, 256, FUSED_SMEM>>>(h, srcI, dstI, ln_w, ln_b, W2, b2, out);
}

// round 16
// speedup vs baseline: 1.1580x; 1.1580x over previous
#include <cuda_runtime.h>
#include <cuda_fp16.h>
#include <cstdint>

#define NN 21
#define D 256
#define GH 512
#define NE 40
#define NB 8192
#define M_TOTAL (NB * NN)     /* 172032 */
#define NCAT 1280
#define NT8 (NCAT / 8)        /* 160 col-tiles per 8-row group */
#define LN_EPS 1e-5f

#define MT 64                 /* M per CTA */
#define NTC 256               /* N chunk */

#define A_STRH 264
#define SZ_A (MT * A_STRH * 2)       /* 33792 B */
#define GEMM_SMEM SZ_A

#define EBPC 2

// ---------------- scratch ----------------
/* Y tiled: half index = ((r>>3)*NT8 + (c>>3))*64 + (r&7)*8 + (c&7) */
__device__ __half g_Y[(size_t)M_TOTAL * NCAT];
/* B fragment-major: tile (nt,kt): nt=0..159, kt=0..15; half off =
   (nt*16+kt)*128 + lane*4 + word*2 + pos  (lane=cin*4+((kk&7)>>1), word=kk>>3, pos=kk&1) */
__device__ __half g_WB[(size_t)NCAT * D];
__device__ float  g_bias[NCAT];
__device__ int    g_bStart[NN + 1];
__device__ int    g_bEdge[NE];

// ---------------- helpers ----------------
__device__ __forceinline__ float gelu_t(float x) {
    float u = 0.7978845608f * fmaf(0.044715f * x, x * x, x);
    float e = __expf(2.f * u);
    float th = 1.f - __fdividef(2.f, e + 1.f);
    return 0.5f * x * (1.f + th);
}
__device__ __forceinline__ void mma16(float* d, const unsigned* a, const unsigned* b) {
    asm volatile(
        "mma.sync.aligned.m16n8k16.row.col.f32.f16.f16.f32 "
        "{%0,%1,%2,%3}, {%4,%5,%6,%7}, {%8,%9}, {%0,%1,%2,%3};\n"
        : "+f"(d[0]), "+f"(d[1]), "+f"(d[2]), "+f"(d[3])
        : "r"(a[0]), "r"(a[1]), "r"(a[2]), "r"(a[3]), "r"(b[0]), "r"(b[1]));
}
__device__ __forceinline__ void ldsm4(unsigned* r, uint32_t addr) {
    asm volatile("ldmatrix.sync.aligned.m8n8.x4.shared.b16 {%0,%1,%2,%3}, [%4];"
        : "=r"(r[0]), "=r"(r[1]), "=r"(r[2]), "=r"(r[3]) : "r"(addr));
}

// ---------------- kernel 0: weights (fragment-major fp16) + bias + buckets ----------------
__global__ void prep_kernel(const float* __restrict__ Wv, const float* __restrict__ bv,
                            const float* __restrict__ W1, const float* __restrict__ b1,
                            const int* __restrict__ srcI, const int* __restrict__ dstI) {
    int idx = blockIdx.x * blockDim.x + threadIdx.x;
    if (idx < D * NCAT) {
        int k = idx / NCAT, n = idx % NCAT;
        float w;
        if (n < 256)      w = Wv[k * 256 + n];
        else if (n < 768) w = W1[k * 512 + (n - 256)];
        else              w = W1[(256 + k) * 512 + (n - 768)];
        int nt = n >> 3, cin = n & 7, kt = k >> 4, kk = k & 15;
        int lane = cin * 4 + ((kk & 7) >> 1);
        int word = kk >> 3, pos = kk & 1;
        size_t off = (size_t)(nt * 16 + kt) * 128 + lane * 4 + word * 2 + pos;
        g_WB[off] = __float2half_rn(w);
    }
    if (idx < NCAT)
        g_bias[idx] = (idx < 256) ? bv[idx] : (idx < 768 ? b1[idx - 256] : 0.f);
    if (blockIdx.x == 0 && threadIdx.x == 0) {
        int cnt[NN];
        for (int n = 0; n < NN; n++) cnt[n] = 0;
        for (int e = 0; e < NE; e++) cnt[dstI[e]]++;
        g_bStart[0] = 0;
        for (int n = 0; n < NN; n++) g_bStart[n + 1] = g_bStart[n] + cnt[n];
        int pos[NN];
        for (int n = 0; n < NN; n++) pos[n] = g_bStart[n];
        for (int e = 0; e < NE; e++) g_bEdge[pos[dstI[e]]++] = e;
    }
}

// ---------------- kernel 1: fused LN + fp16 GEMM (B direct from L2, barrier-free loop) ----------------
__global__ __launch_bounds__(256, 2) void gemm_ln_kernel(
    const float* __restrict__ h, const float* __restrict__ lnw, const float* __restrict__ lnb) {
    extern __shared__ __align__(16) char smem[];
    __half* sA = (__half*)smem;
    const int tid = threadIdx.x, warp = tid >> 5, lane = tid & 31;
    const int wm = warp & 1, wn = warp >> 1;          /* warp tile 32 rows x 64 cols */
    const int gq = lane >> 2, t = lane & 3;
    const int mBase = blockIdx.x * MT;
    const uint32_t sAu = (uint32_t)__cvta_generic_to_shared(sA);

    /* fused LayerNorm: warp per row, fp16 into sA */
    {
        float4 w0 = ((const float4*)lnw)[2 * lane], w1 = ((const float4*)lnw)[2 * lane + 1];
        float4 bb0 = ((const float4*)lnb)[2 * lane], bb1 = ((const float4*)lnb)[2 * lane + 1];
        #pragma unroll 2
        for (int it = 0; it < 8; it++) {
            int row = warp * 8 + it;
            const float4* r4 = (const float4*)(h + (size_t)(mBase + row) * D);
            float4 va = r4[2 * lane], vb = r4[2 * lane + 1];
            float s = va.x + va.y + va.z + va.w + vb.x + vb.y + vb.z + vb.w;
            float q = va.x*va.x + va.y*va.y + va.z*va.z + va.w*va.w
                    + vb.x*vb.x + vb.y*vb.y + vb.z*vb.z + vb.w*vb.w;
            #pragma unroll
            for (int off = 16; off; off >>= 1) {
                s += __shfl_xor_sync(0xffffffffu, s, off);
                q += __shfl_xor_sync(0xffffffffu, q, off);
            }
            float mu = s * (1.f / D);
            float var = q * (1.f / D) - mu * mu;
            float inv = rsqrtf(var + LN_EPS);
            __half2 h0 = __floats2half2_rn((va.x - mu) * inv * w0.x + bb0.x,
                                           (va.y - mu) * inv * w0.y + bb0.y);
            __half2 h1 = __floats2half2_rn((va.z - mu) * inv * w0.z + bb0.z,
                                           (va.w - mu) * inv * w0.w + bb0.w);
            __half2 h2 = __floats2half2_rn((vb.x - mu) * inv * w1.x + bb1.x,
                                           (vb.y - mu) * inv * w1.y + bb1.y);
            __half2 h3 = __floats2half2_rn((vb.z - mu) * inv * w1.z + bb1.z,
                                           (vb.w - mu) * inv * w1.w + bb1.w);
            uint4 o;
            o.x = *(unsigned*)&h0; o.y = *(unsigned*)&h1;
            o.z = *(unsigned*)&h2; o.w = *(unsigned*)&h3;
            *(uint4*)(sA + row * A_STRH + lane * 8) = o;
        }
    }
    __syncthreads();       /* only barrier: sA ready for all warps */

    const int lm = lane >> 3, lr = lane & 7;
    uint32_t aBase[2];
    #pragma unroll
    for (int mi = 0; mi < 2; mi++)
        aBase[mi] = sAu + (uint32_t)(((wm * 32 + mi * 16 + (lm & 1) * 8 + lr) * A_STRH
                                      + (lm >> 1) * 8) * 2);

    /* B tiles for this warp: nt = chunk*32 + wn*8 + nj, kt = s16 (0..15) */
    uint2 bf[2][8];
    const char* bWarp0 = (const char*)g_WB + (size_t)lane * 8;  /* + tile*256 */
    {   /* prefetch chunk 0, step 0 */
        const char* bp = bWarp0 + (size_t)(wn * 8) * 16 * 256;
        #pragma unroll
        for (int nj = 0; nj < 8; nj++)
            bf[0][nj] = __ldg((const uint2*)(bp + nj * 4096));
    }

    float c[2][8][4];
    #pragma unroll 1
    for (int chunk = 0; chunk < 5; chunk++) {
        const char* bp = bWarp0 + (size_t)(chunk * 32 + wn * 8) * 16 * 256;
        #pragma unroll
        for (int mi = 0; mi < 2; mi++)
            #pragma unroll
            for (int ni = 0; ni < 8; ni++)
                #pragma unroll
                for (int j = 0; j < 4; j++) c[mi][ni][j] = 0.f;

        #pragma unroll 4
        for (int s16 = 0; s16 < 16; s16++) {
            int cur = s16 & 1;
            /* prefetch next step (next chunk's step 0 when s16==15) */
            if (s16 < 15) {
                const char* np = bp + (s16 + 1) * 256;
                #pragma unroll
                for (int nj = 0; nj < 8; nj++)
                    bf[cur ^ 1][nj] = __ldg((const uint2*)(np + nj * 4096));
            } else if (chunk < 4) {
                const char* np = bWarp0 + (size_t)((chunk + 1) * 32 + wn * 8) * 16 * 256;
                #pragma unroll
                for (int nj = 0; nj < 8; nj++)
                    bf[cur ^ 1][nj] = __ldg((const uint2*)(np + nj * 4096));
            }
            unsigned af[2][4];
            uint32_t ka = (uint32_t)(s16 * 32);
            ldsm4(af[0], aBase[0] + ka);
            ldsm4(af[1], aBase[1] + ka);
            #pragma unroll
            for (int mi = 0; mi < 2; mi++)
                #pragma unroll
                for (int nj = 0; nj < 8; nj++)
                    mma16(c[mi][nj], af[mi], (const unsigned*)&bf[cur][nj]);
        }

        /* epilogue: bias + tiled coalesced fp16 store */
        {
            int nBase = chunk * NTC;
            #pragma unroll
            for (int mi = 0; mi < 2; mi++)
                #pragma unroll
                for (int ni = 0; ni < 8; ni++) {
                    int r0 = mBase + wm * 32 + mi * 16 + gq;
                    int cT = nBase + wn * 64 + ni * 8;
                    int cb = cT + 2 * t;
                    float b0v = g_bias[cb], b1v = g_bias[cb + 1];
                    size_t off = ((size_t)(r0 >> 3) * NT8 + (cT >> 3)) * 64 + gq * 8 + 2 * t;
                    *(__half2*)(g_Y + off) =
                        __floats2half2_rn(c[mi][ni][0] + b0v, c[mi][ni][1] + b1v);
                    *(__half2*)(g_Y + off + (size_t)NT8 * 64) =
                        __floats2half2_rn(c[mi][ni][2] + b0v, c[mi][ni][3] + b1v);
                }
        }
    }
}

// ---------------- kernel 2: gates + scatter + residual (unchanged from R13) ----------------
__global__ __launch_bounds__(512) void edge_kernel(const float* __restrict__ h,
                                                   const int* __restrict__ srcI,
                                                   const int* __restrict__ dstI,
                                                   const float* __restrict__ W2,
                                                   const float* __restrict__ b2,
                                                   float* __restrict__ out) {
    __shared__ __half sV[EBPC * NN * D];
    __shared__ float  sGate[EBPC * NE];
    __shared__ float  sW2[GH];
    __shared__ int sSrc[NE], sDst[NE], sBS[NN + 1], sBE[NE];
    int b0 = blockIdx.x * EBPC;
    int tid = threadIdx.x;
    if (tid < NE) { sSrc[tid] = srcI[tid]; sDst[tid] = dstI[tid]; sBE[tid] = g_bEdge[tid]; }
    if (tid >= 64 && tid < 64 + NN + 1) sBS[tid - 64] = g_bStart[tid - 64];
    if (tid >= 128 && tid < 256) ((float4*)sW2)[tid - 128] = ((const float4*)W2)[tid - 128];
    const uint4* Yq = (const uint4*)g_Y;
    #pragma unroll 1
    for (int i = tid; i < EBPC * NN * 32; i += 512) {
        int r = i >> 5, cc = i & 31;
        int gr = b0 * NN + r;
        ((uint4*)sV)[i] = Yq[((size_t)(gr >> 3) * NT8 + cc) * 8 + (gr & 7)];
    }
    __syncthreads();

    int warp = tid >> 5, lane = tid & 31;
    float b2v = __ldg(b2);
    #pragma unroll 1
    for (int kk = 0; kk < 5; kk++) {
        int combo = warp + (kk << 4);
        int be = combo / NE, e = combo - be * NE;
        int gS = (b0 + be) * NN + sSrc[e];
        int gD = (b0 + be) * NN + sDst[e];
        size_t baseS = (size_t)(gS >> 3) * NT8 * 8 + (gS & 7);
        size_t baseD = (size_t)(gD >> 3) * NT8 * 8 + (gD & 7);
        float sum = 0.f;
        #pragma unroll
        for (int i = lane; i < 64; i += 32) {
            uint4 ua = __ldg(Yq + baseS + (size_t)(32 + i) * 8);
            uint4 ub = __ldg(Yq + baseD + (size_t)(96 + i) * 8);
            const float* wv = sW2 + i * 8;
            __half2 t0 = __hadd2(*(__half2*)&ua.x, *(__half2*)&ub.x);
            __half2 t1 = __hadd2(*(__half2*)&ua.y, *(__half2*)&ub.y);
            __half2 t2 = __hadd2(*(__half2*)&ua.z, *(__half2*)&ub.z);
            __half2 t3 = __hadd2(*(__half2*)&ua.w, *(__half2*)&ub.w);
            float2 f0 = __half22float2(t0), f1 = __half22float2(t1);
            float2 f2 = __half22float2(t2), f3 = __half22float2(t3);
            sum += gelu_t(f0.x) * wv[0] + gelu_t(f0.y) * wv[1];
            sum += gelu_t(f1.x) * wv[2] + gelu_t(f1.y) * wv[3];
            sum += gelu_t(f2.x) * wv[4] + gelu_t(f2.y) * wv[5];
            sum += gelu_t(f3.x) * wv[6] + gelu_t(f3.y) * wv[7];
        }
        #pragma unroll
        for (int off = 16; off; off >>= 1) sum += __shfl_xor_sync(0xffffffffu, sum, off);
        if (!lane) sGate[combo] = 1.f / (1.f + __expf(-(sum + b2v)));
    }
    __syncthreads();

    const float* hb = h + (size_t)b0 * NN * D;
    float* ob = out + (size_t)b0 * NN * D;
    int col = tid & 63, slot = tid >> 6;
    #pragma unroll 1
    for (int task = slot; task < EBPC * NN; task += 8) {
        int be = task / NN, n = task - be * NN;
        int r = be * NN + n;
        float4 acc = ((const float4*)(hb + r * D))[col];
        int jEnd = sBS[n + 1];
        for (int jj = sBS[n]; jj < jEnd; jj++) {
            int e = sBE[jj];
            float gte = sGate[be * NE + e];
            uint2 u = *(const uint2*)(sV + (be * NN + sSrc[e]) * D + col * 4);
            float2 lo = __half22float2(*(__half2*)&u.x);
            float2 hi = __half22float2(*(__half2*)&u.y);
            acc.x += gte * lo.x; acc.y += gte * lo.y;
            acc.z += gte * hi.x; acc.w += gte * hi.y;
        }
        ((float4*)(ob + r * D))[col] = acc;
    }
}

// ---------------- launcher ----------------
extern "C" void kernel_launch(void* const* d_in, const int* in_sizes, int n_in,
                              void* d_out, int out_size) {
    const float* h    = (const float*)d_in[0];
    const int*   srcI = (const int*)d_in[1];
    const int*   dstI = (const int*)d_in[2];
    const float* ln_w = (const float*)d_in[3];
    const float* ln_b = (const float*)d_in[4];
    const float* Wv   = (const float*)d_in[5];
    const float* bv   = (const float*)d_in[6];
    const float* W1   = (const float*)d_in[7];
    const float* b1   = (const float*)d_in[8];
    const float* W2   = (const float*)d_in[9];
    const float* b2   = (const float*)d_in[10];
    float* out = (float*)d_out;

    cudaFuncSetAttribute(gemm_ln_kernel, cudaFuncAttributeMaxDynamicSharedMemorySize, GEMM_SMEM);

    prep_kernel<<<(D * NCAT + 255) / 256, 256>>>(Wv, bv, W1, b1, srcI, dstI);
    gemm_ln_kernel<<<M_TOTAL / MT, 256, GEMM_SMEM>>>(h, ln_w, ln_b);
    edge_kernel<<<NB / EBPC, 512>>>(h, srcI, dstI, W2, b2, out);
}